// round 10
// baseline (speedup 1.0000x reference)
#include <cuda_runtime.h>
#include <cuda_bf16.h>
#include <cuda_fp16.h>
#include <math.h>

// Problem constants
#define PP   256
#define FF   20
#define HH   18
#define WW   18
#define HW   (HH*WW)      // 324
#define VOL  (FF*HH*WW)   // 6480
#define MAXB 4096
#define PI_F 3.14159f

// Sampler pair volume: per layer 21 rows x 21 half2, 20 layers
#define PROW 21
#define PLAY (PROW*PROW)  // 441
#define PVOL (FF*PLAY)    // 8820 half2 = 35280 B

// Device scratch
__device__ float g_h[MAXB * PP];
__device__ float g_params[MAXB * FF * 5];   // c, s, scale, tx, ty

// ---------------------------------------------------------------------------
// f32x2 helpers (FFMA2 via PTX)
// ---------------------------------------------------------------------------
typedef unsigned long long u64;

__device__ __forceinline__ u64 pack2(float lo, float hi) {
    u64 d;
    asm("mov.b64 %0, {%1, %2};" : "=l"(d)
        : "r"(__float_as_uint(lo)), "r"(__float_as_uint(hi)));
    return d;
}
__device__ __forceinline__ u64 pack2dup(float v) {
    u64 d;
    asm("mov.b64 %0, {%1, %1};" : "=l"(d) : "r"(__float_as_uint(v)));
    return d;
}
__device__ __forceinline__ u64 fma2(u64 a, u64 b, u64 c) {
    u64 d;
    asm("fma.rn.f32x2 %0, %1, %2, %3;" : "=l"(d) : "l"(a), "l"(b), "l"(c));
    return d;
}
__device__ __forceinline__ float2 unpack2(u64 v) {
    unsigned lo, hi;
    asm("mov.b64 {%0, %1}, %2;" : "=r"(lo), "=r"(hi) : "l"(v));
    float2 f; f.x = __uint_as_float(lo); f.y = __uint_as_float(hi);
    return f;
}

// ---------------------------------------------------------------------------
// Kernel 1: h = relu(pc @ W1 + b1) — tiled SGEMM (R5, proven ~23 us)
// BM=64, BN=64, BK=32, 256 threads, 4x4 thread tile. grid = (B/64, 4)
// ---------------------------------------------------------------------------
#define K1_BM 64
#define K1_BN 64
#define K1_BK 32
#define K1_AS 68

__global__ __launch_bounds__(256) void adaat_hidden_kernel(
    const float* __restrict__ pc, int B,
    const float* __restrict__ W1, const float* __restrict__ b1)
{
    __shared__ float As[K1_BK * K1_AS];
    __shared__ float Bs[K1_BK * K1_AS];

    const int b0  = blockIdx.x * K1_BM;
    const int n0  = blockIdx.y * K1_BN;
    const int tid = threadIdx.x;
    const int tc  = tid & 15;
    const int tr  = tid >> 4;

    u64 acc[4][2];
    {
        float4 bj = *(const float4*)(b1 + n0 + tc * 4);
        u64 lo = pack2(bj.x, bj.y), hi = pack2(bj.z, bj.w);
        #pragma unroll
        for (int i = 0; i < 4; i++) { acc[i][0] = lo; acc[i][1] = hi; }
    }

    for (int kt = 0; kt < PP; kt += K1_BK) {
        #pragma unroll
        for (int p = 0; p < 8; p++) {
            int idx = p * 256 + tid;
            int row = idx >> 5;
            int kk  = idx & 31;
            float v = (b0 + row < B) ? pc[(size_t)(b0 + row) * PP + kt + kk] : 0.f;
            As[kk * K1_AS + row] = v;
        }
        #pragma unroll
        for (int p = 0; p < 8; p++) {
            int idx = p * 256 + tid;
            int kk  = idx >> 6;
            int col = idx & 63;
            Bs[kk * K1_AS + col] = W1[(size_t)(kt + kk) * PP + n0 + col];
        }
        __syncthreads();

        #pragma unroll
        for (int kk = 0; kk < K1_BK; kk++) {
            float4 a = *(const float4*)(As + kk * K1_AS + tr * 4);
            float4 w = *(const float4*)(Bs + kk * K1_AS + tc * 4);
            u64 wlo = pack2(w.x, w.y), whi = pack2(w.z, w.w);
            u64 a0 = pack2dup(a.x), a1 = pack2dup(a.y);
            u64 a2 = pack2dup(a.z), a3 = pack2dup(a.w);
            acc[0][0] = fma2(a0, wlo, acc[0][0]); acc[0][1] = fma2(a0, whi, acc[0][1]);
            acc[1][0] = fma2(a1, wlo, acc[1][0]); acc[1][1] = fma2(a1, whi, acc[1][1]);
            acc[2][0] = fma2(a2, wlo, acc[2][0]); acc[2][1] = fma2(a2, whi, acc[2][1]);
            acc[3][0] = fma2(a3, wlo, acc[3][0]); acc[3][1] = fma2(a3, whi, acc[3][1]);
        }
        __syncthreads();
    }

    #pragma unroll
    for (int i = 0; i < 4; i++) {
        int row = b0 + tr * 4 + i;
        if (row >= B) break;
        float2 v0 = unpack2(acc[i][0]);
        float2 v1 = unpack2(acc[i][1]);
        float4 o;
        o.x = fmaxf(v0.x, 0.f); o.y = fmaxf(v0.y, 0.f);
        o.z = fmaxf(v1.x, 0.f); o.w = fmaxf(v1.y, 0.f);
        *(float4*)(g_h + (size_t)row * PP + n0 + tc * 4) = o;
    }
}

// ---------------------------------------------------------------------------
// Kernel 2: heads — (B x 80) = h @ [Ws|Wr|Wt] + bias, activations -> g_params.
// BM=16 rows/block -> 256 blocks, 160 threads, 2-row x 4-col tile.
// ---------------------------------------------------------------------------
#define H2_BM  16
#define H2_HS  18

__device__ __forceinline__ float4 head_bias(int cg,
    const float* bs, const float* br, const float* bt)
{
    if (cg < 5)  return ((const float4*)bs)[cg];
    if (cg < 10) return ((const float4*)br)[cg - 5];
    return ((const float4*)bt)[cg - 10];
}

__device__ __forceinline__ void head_store(int row, int B, int cg, const float* o4)
{
    if (row >= B) return;
    float* pb = g_params + (size_t)row * (FF * 5);
    if (cg < 5) {
        #pragma unroll
        for (int ci = 0; ci < 4; ci++)
            pb[(cg * 4 + ci) * 5 + 2] = 2.f / (1.f + expf(-o4[ci]));
    } else if (cg < 10) {
        #pragma unroll
        for (int ci = 0; ci < 4; ci++) {
            float ang = tanhf(o4[ci]) * PI_F;
            int f = (cg - 5) * 4 + ci;
            pb[f * 5 + 0] = cosf(ang);
            pb[f * 5 + 1] = sinf(ang);
        }
    } else {
        #pragma unroll
        for (int ci = 0; ci < 4; ci++) {
            int o = (cg - 10) * 4 + ci;
            pb[(o >> 1) * 5 + 3 + (o & 1)] = tanhf(o4[ci]);
        }
    }
}

__global__ __launch_bounds__(160) void adaat_heads_kernel(
    int B,
    const float* __restrict__ Ws, const float* __restrict__ bs,
    const float* __restrict__ Wr, const float* __restrict__ br,
    const float* __restrict__ Wt, const float* __restrict__ bt)
{
    __shared__ float hs[PP * H2_HS];
    __shared__ float Wss[32 * 80];

    const int b0  = blockIdx.x * H2_BM;
    const int tid = threadIdx.x;

    for (int idx = tid; idx < H2_BM * PP; idx += 160) {
        int row = idx >> 8;
        int k   = idx & (PP - 1);
        float v = (b0 + row < B) ? g_h[(size_t)(b0 + row) * PP + k] : 0.f;
        hs[k * H2_HS + row] = v;
    }

    const int rp = tid / 20;
    const int cg = tid - rp * 20;

    float o0[4], o1[4];
    {
        float4 bb = head_bias(cg, bs, br, bt);
        o0[0] = bb.x; o0[1] = bb.y; o0[2] = bb.z; o0[3] = bb.w;
        o1[0] = bb.x; o1[1] = bb.y; o1[2] = bb.z; o1[3] = bb.w;
    }

    for (int kt = 0; kt < PP; kt += 32) {
        #pragma unroll
        for (int p = 0; p < 16; p++) {
            int idx = p * 160 + tid;
            int kk  = idx / 80;
            int c   = idx - kk * 80;
            int k   = kt + kk;
            float v;
            if (c < 20)      v = Ws[(size_t)k * 20 + c];
            else if (c < 40) v = Wr[(size_t)k * 20 + (c - 20)];
            else             v = Wt[(size_t)k * 40 + (c - 40)];
            Wss[kk * 80 + c] = v;
        }
        __syncthreads();

        #pragma unroll 8
        for (int kk = 0; kk < 32; kk++) {
            float2 h2 = *(const float2*)(hs + (kt + kk) * H2_HS + rp * 2);
            float4 w  = *(const float4*)(Wss + kk * 80 + cg * 4);
            o0[0] = fmaf(h2.x, w.x, o0[0]);
            o0[1] = fmaf(h2.x, w.y, o0[1]);
            o0[2] = fmaf(h2.x, w.z, o0[2]);
            o0[3] = fmaf(h2.x, w.w, o0[3]);
            o1[0] = fmaf(h2.y, w.x, o1[0]);
            o1[1] = fmaf(h2.y, w.y, o1[1]);
            o1[2] = fmaf(h2.y, w.z, o1[2]);
            o1[3] = fmaf(h2.y, w.w, o1[3]);
        }
        __syncthreads();
    }

    head_store(b0 + rp * 2,     B, cg, o0);
    head_store(b0 + rp * 2 + 1, B, cg, o1);
}

// ---------------------------------------------------------------------------
// Kernel 3: trilinear sample — R4-exact (proven 70.4 us). One CTA per batch,
// block (18,18). half2 pair volume with zero border. NO minBlocks clause.
// ---------------------------------------------------------------------------
__global__ __launch_bounds__(324) void adaat_sample_kernel(
    const float* __restrict__ fm, float* __restrict__ out)
{
    const int b   = blockIdx.x;
    const int tx  = threadIdx.x;      // 0..17
    const int ty  = threadIdx.y;      // 0..17
    const int tid = ty * WW + tx;

    __shared__ __half2 pairs[PVOL];   // 35280 B
    __shared__ float4  cfA[FF];       // axx, axy, cx, zw0
    __shared__ float4  cfB[FF];       // ayx, ayy, cy, zw1
    __shared__ int2    zb[FF];

    {
        float4* p4 = (float4*)pairs;
        for (int i = tid; i < PVOL / 4; i += HW)
            p4[i] = make_float4(0.f, 0.f, 0.f, 0.f);
    }
    __syncthreads();

    {
        const float* src = fm + (size_t)b * VOL + ty * WW + tx;
        __half2* dst = pairs + (ty + 1) * PROW + (tx + 1);
        #pragma unroll
        for (int z = 0; z < FF; z++) {
            float val   = src[z * HW];
            float right = (tx < WW - 1) ? src[z * HW + 1] : 0.f;
            dst[z * PLAY] = __floats2half2_rn(val, right);
            if (tx == 0)
                pairs[z * PLAY + (ty + 1) * PROW] = __floats2half2_rn(0.f, val);
        }
    }

    if (tid < FF) {
        const float* p = g_params + (size_t)(b * FF + tid) * 5;
        float c = p[0], s = p[1], sc = p[2], txp = p[3], typ = p[4];
        float kk  = sc * ((float)WW / (WW - 1));
        float axx = c * kk,  axy = -s * kk;
        float ayx = s * kk,  ayy =  c * kk;
        float cx = (WW * 0.5f) * (txp - sc * c + sc * s) + (WW - 1) * 0.5f;
        float cy = (HH * 0.5f) * (typ - sc * s - sc * c) + (HH - 1) * 0.5f;

        float iz  = (float)tid * ((float)FF / (FF - 1)) - 0.5f;
        float z0f = floorf(iz);
        float wz  = iz - z0f;
        int   z0  = (int)z0f, z1 = z0 + 1;
        float w0  = (z0 >= 0 && z0 < FF) ? (1.f - wz) : 0.f;
        float w1  = (z1 >= 0 && z1 < FF) ? wz         : 0.f;
        int   zb0 = min(max(z0, 0), FF - 1) * PLAY;
        int   zb1 = min(max(z1, 0), FF - 1) * PLAY;

        cfA[tid] = make_float4(axx, axy, cx, w0);
        cfB[tid] = make_float4(ayx, ayy, cy, w1);
        zb[tid]  = make_int2(zb0, zb1);
    }
    __syncthreads();

    const float fx = (float)tx, fy = (float)ty;
    float* outb = out + (size_t)b * VOL + tid;

    #pragma unroll 4
    for (int f = 0; f < FF; f++) {
        float4 A  = cfA[f];
        float4 Bv = cfB[f];
        int2   zo = zb[f];

        float ix = fmaf(A.x,  fx, fmaf(A.y,  fy, A.z));
        float iy = fmaf(Bv.x, fx, fmaf(Bv.y, fy, Bv.z));
        ix = fminf(fmaxf(ix, -1.f), (float)WW);
        iy = fminf(fmaxf(iy, -1.f), (float)HH);

        int   x0 = __float2int_rd(ix);
        int   y0 = __float2int_rd(iy);
        float wx = ix - (float)x0;
        float wy = iy - (float)y0;

        int bo = y0 * PROW + x0 + (PROW + 1);

        float2 f00 = __half22float2(pairs[zo.x + bo]);
        float2 f01 = __half22float2(pairs[zo.x + bo + PROW]);
        float2 f10 = __half22float2(pairs[zo.y + bo]);
        float2 f11 = __half22float2(pairs[zo.y + bo + PROW]);

        float h00 = fmaf(wx, f00.y - f00.x, f00.x);
        float h01 = fmaf(wx, f01.y - f01.x, f01.x);
        float h10 = fmaf(wx, f10.y - f10.x, f10.x);
        float h11 = fmaf(wx, f11.y - f11.x, f11.x);

        float s0 = fmaf(wy, h01 - h00, h00);
        float s1 = fmaf(wy, h11 - h10, h10);

        outb[f * HW] = fmaf(A.w, s0, Bv.w * s1);
    }
}

// ---------------------------------------------------------------------------
// Launch
// ---------------------------------------------------------------------------
extern "C" void kernel_launch(void* const* d_in, const int* in_sizes, int n_in,
                              void* d_out, int out_size)
{
    const float* feature_map = (const float*)d_in[0];
    const float* para_code   = (const float*)d_in[1];
    const float* W1          = (const float*)d_in[2];
    const float* b1          = (const float*)d_in[3];
    const float* Ws          = (const float*)d_in[4];
    const float* bs          = (const float*)d_in[5];
    const float* Wr          = (const float*)d_in[6];
    const float* br          = (const float*)d_in[7];
    const float* Wt          = (const float*)d_in[8];
    const float* bt          = (const float*)d_in[9];
    float*       out         = (float*)d_out;

    int B = in_sizes[1] / PP;
    if (B > MAXB) B = MAXB;

    dim3 g1((B + K1_BM - 1) / K1_BM, PP / K1_BN);
    adaat_hidden_kernel<<<g1, 256>>>(para_code, B, W1, b1);
    adaat_heads_kernel<<<(B + H2_BM - 1) / H2_BM, 160>>>(B, Ws, bs, Wr, br, Wt, bt);
    adaat_sample_kernel<<<B, dim3(WW, HH)>>>(feature_map, out);
}

// round 11
// speedup vs baseline: 1.2761x; 1.2761x over previous
#include <cuda_runtime.h>
#include <cuda_bf16.h>
#include <cuda_fp16.h>
#include <math.h>

// Problem constants
#define PP   256
#define FF   20
#define HH   18
#define WW   18
#define HW   (HH*WW)      // 324
#define VOL  (FF*HH*WW)   // 6480
#define MAXB 4096
#define PI_F 3.14159f

// Sampler pair volume: per layer 21 rows x 21 half2, 20 layers
#define PROW 21
#define PLAY (PROW*PROW)  // 441
#define PVOL (FF*PLAY)    // 8820 half2 = 35280 B

// Head partials: 4 k-groups x B rows x 80 cols (fp32)
#define NG 4
__device__ float g_part[NG][MAXB * 80];

// ---------------------------------------------------------------------------
// f32x2 helpers (FFMA2 via PTX)
// ---------------------------------------------------------------------------
typedef unsigned long long u64;

__device__ __forceinline__ u64 pack2(float lo, float hi) {
    u64 d;
    asm("mov.b64 %0, {%1, %2};" : "=l"(d)
        : "r"(__float_as_uint(lo)), "r"(__float_as_uint(hi)));
    return d;
}
__device__ __forceinline__ u64 pack2dup(float v) {
    u64 d;
    asm("mov.b64 %0, {%1, %1};" : "=l"(d) : "r"(__float_as_uint(v)));
    return d;
}
__device__ __forceinline__ u64 fma2(u64 a, u64 b, u64 c) {
    u64 d;
    asm("fma.rn.f32x2 %0, %1, %2, %3;" : "=l"(d) : "l"(a), "l"(b), "l"(c));
    return d;
}
__device__ __forceinline__ float2 unpack2(u64 v) {
    unsigned lo, hi;
    asm("mov.b64 {%0, %1}, %2;" : "=r"(lo), "=r"(hi) : "l"(v));
    float2 f; f.x = __uint_as_float(lo); f.y = __uint_as_float(hi);
    return f;
}

// ---------------------------------------------------------------------------
// Kernel 1: fused hidden + head partials.
// Main: h_tile[64 rows][64 cols] = relu(pc @ W1 + b1) slice (R5-proven GEMM).
// Epilogue: g_part[n0g][row][80] = h_tile @ Whead[n0.. n0+64][80].
// grid = (B/64, 4), 256 threads.
// ---------------------------------------------------------------------------
#define K1_BM 64
#define K1_BN 64
#define K1_BK 32
#define K1_AS 68
#define HS_S  66      // h-tile smem stride

__global__ __launch_bounds__(256) void adaat_hidden_kernel(
    const float* __restrict__ pc, int B,
    const float* __restrict__ W1, const float* __restrict__ b1,
    const float* __restrict__ Ws, const float* __restrict__ Wr,
    const float* __restrict__ Wt)
{
    // pool: main loop uses As = pool[0:2176), Bs = pool[2176:4352)
    //       epilogue reuses pool as hs[col][row] (64*66 = 4224 floats)
    __shared__ float pool[4352];
    __shared__ float Wh[64 * 80];     // head-weight slice (20.5 KB)
    float* As = pool;
    float* Bs = pool + K1_BK * K1_AS;

    const int b0  = blockIdx.x * K1_BM;
    const int n0  = blockIdx.y * K1_BN;
    const int tid = threadIdx.x;
    const int tc  = tid & 15;
    const int tr  = tid >> 4;

    // stage head-weight slice: Wh[kk][c], kk = local k (h col), c = head col
    #pragma unroll
    for (int p = 0; p < 20; p++) {
        int i  = p * 256 + tid;
        int kk = i / 80;
        int c  = i - kk * 80;
        int gk = n0 + kk;
        float v;
        if (c < 20)      v = Ws[(size_t)gk * 20 + c];
        else if (c < 40) v = Wr[(size_t)gk * 20 + (c - 20)];
        else             v = Wt[(size_t)gk * 40 + (c - 40)];
        Wh[kk * 80 + c] = v;
    }

    // ---- main GEMM ----
    u64 acc[4][2];
    {
        float4 bj = *(const float4*)(b1 + n0 + tc * 4);
        u64 lo = pack2(bj.x, bj.y), hi = pack2(bj.z, bj.w);
        #pragma unroll
        for (int i = 0; i < 4; i++) { acc[i][0] = lo; acc[i][1] = hi; }
    }

    for (int kt = 0; kt < PP; kt += K1_BK) {
        #pragma unroll
        for (int p = 0; p < 8; p++) {
            int idx = p * 256 + tid;
            int row = idx >> 5;
            int kk  = idx & 31;
            float v = (b0 + row < B) ? pc[(size_t)(b0 + row) * PP + kt + kk] : 0.f;
            As[kk * K1_AS + row] = v;
        }
        #pragma unroll
        for (int p = 0; p < 8; p++) {
            int idx = p * 256 + tid;
            int kk  = idx >> 6;
            int col = idx & 63;
            Bs[kk * K1_AS + col] = W1[(size_t)(kt + kk) * PP + n0 + col];
        }
        __syncthreads();

        #pragma unroll
        for (int kk = 0; kk < K1_BK; kk++) {
            float4 a = *(const float4*)(As + kk * K1_AS + tr * 4);
            float4 w = *(const float4*)(Bs + kk * K1_AS + tc * 4);
            u64 wlo = pack2(w.x, w.y), whi = pack2(w.z, w.w);
            u64 a0 = pack2dup(a.x), a1 = pack2dup(a.y);
            u64 a2 = pack2dup(a.z), a3 = pack2dup(a.w);
            acc[0][0] = fma2(a0, wlo, acc[0][0]); acc[0][1] = fma2(a0, whi, acc[0][1]);
            acc[1][0] = fma2(a1, wlo, acc[1][0]); acc[1][1] = fma2(a1, whi, acc[1][1]);
            acc[2][0] = fma2(a2, wlo, acc[2][0]); acc[2][1] = fma2(a2, whi, acc[2][1]);
            acc[3][0] = fma2(a3, wlo, acc[3][0]); acc[3][1] = fma2(a3, whi, acc[3][1]);
        }
        __syncthreads();
    }

    // ---- relu + spill h tile to smem: hs[col][row] ----
    float* hs = pool;
    #pragma unroll
    for (int i = 0; i < 4; i++) {
        float2 v0 = unpack2(acc[i][0]);
        float2 v1 = unpack2(acc[i][1]);
        int row = tr * 4 + i;
        hs[(tc * 4 + 0) * HS_S + row] = fmaxf(v0.x, 0.f);
        hs[(tc * 4 + 1) * HS_S + row] = fmaxf(v0.y, 0.f);
        hs[(tc * 4 + 2) * HS_S + row] = fmaxf(v1.x, 0.f);
        hs[(tc * 4 + 3) * HS_S + row] = fmaxf(v1.y, 0.f);
    }
    __syncthreads();

    // ---- head partials: out[row][80] = hs[:, row] . Wh[:, :] over 64 local k
    // thread: row = tid>>2 (0..63), quarter q = tid&3 -> cols q*20..q*20+19
    {
        const int row = tid >> 2;
        const int q   = tid & 3;
        float accp[20];
        #pragma unroll
        for (int j = 0; j < 20; j++) accp[j] = 0.f;

        #pragma unroll 4
        for (int kk = 0; kk < 64; kk++) {
            float hv = hs[kk * HS_S + row];
            const float* wrow = Wh + kk * 80 + q * 20;
            #pragma unroll
            for (int g = 0; g < 5; g++) {
                float4 w = *(const float4*)(wrow + g * 4);
                accp[g*4+0] = fmaf(hv, w.x, accp[g*4+0]);
                accp[g*4+1] = fmaf(hv, w.y, accp[g*4+1]);
                accp[g*4+2] = fmaf(hv, w.z, accp[g*4+2]);
                accp[g*4+3] = fmaf(hv, w.w, accp[g*4+3]);
            }
        }

        if (b0 + row < B) {
            float* dst = g_part[blockIdx.y] + (size_t)(b0 + row) * 80 + q * 20;
            #pragma unroll
            for (int g = 0; g < 5; g++)
                *(float4*)(dst + g * 4) =
                    make_float4(accp[g*4+0], accp[g*4+1], accp[g*4+2], accp[g*4+3]);
        }
    }
}

// ---------------------------------------------------------------------------
// Kernel 2: trilinear sample — R4-proven body. Coefficient setup now sums the
// 4 head partials + biases and applies activations in-block.
// ---------------------------------------------------------------------------
__global__ __launch_bounds__(324) void adaat_sample_kernel(
    const float* __restrict__ fm, float* __restrict__ out,
    const float* __restrict__ bs, const float* __restrict__ br,
    const float* __restrict__ bt)
{
    const int b   = blockIdx.x;
    const int tx  = threadIdx.x;      // 0..17
    const int ty  = threadIdx.y;      // 0..17
    const int tid = ty * WW + tx;

    __shared__ __half2 pairs[PVOL];   // 35280 B
    __shared__ float4  cfA[FF];       // axx, axy, cx, zw0
    __shared__ float4  cfB[FF];       // ayx, ayy, cy, zw1
    __shared__ int2    zb[FF];

    {
        float4* p4 = (float4*)pairs;
        for (int i = tid; i < PVOL / 4; i += HW)
            p4[i] = make_float4(0.f, 0.f, 0.f, 0.f);
    }
    __syncthreads();

    {
        const float* src = fm + (size_t)b * VOL + ty * WW + tx;
        __half2* dst = pairs + (ty + 1) * PROW + (tx + 1);
        #pragma unroll
        for (int z = 0; z < FF; z++) {
            float val   = src[z * HW];
            float right = (tx < WW - 1) ? src[z * HW + 1] : 0.f;
            dst[z * PLAY] = __floats2half2_rn(val, right);
            if (tx == 0)
                pairs[z * PLAY + (ty + 1) * PROW] = __floats2half2_rn(0.f, val);
        }
    }

    if (tid < FF) {
        const int f = tid;
        // sum partials + bias, then activations
        float rs  = bs[f];
        float rr  = br[f];
        float rtx = bt[2 * f];
        float rty = bt[2 * f + 1];
        #pragma unroll
        for (int p = 0; p < NG; p++) {
            const float* pp = g_part[p] + (size_t)b * 80;
            rs  += pp[f];
            rr  += pp[20 + f];
            rtx += pp[40 + 2 * f];
            rty += pp[41 + 2 * f];
        }
        float sc  = 2.f / (1.f + expf(-rs));
        float ang = tanhf(rr) * PI_F;
        float c   = cosf(ang), s = sinf(ang);
        float txp = tanhf(rtx), typ = tanhf(rty);

        float kk  = sc * ((float)WW / (WW - 1));
        float axx = c * kk,  axy = -s * kk;
        float ayx = s * kk,  ayy =  c * kk;
        float cx = (WW * 0.5f) * (txp - sc * c + sc * s) + (WW - 1) * 0.5f;
        float cy = (HH * 0.5f) * (typ - sc * s - sc * c) + (HH - 1) * 0.5f;

        float iz  = (float)f * ((float)FF / (FF - 1)) - 0.5f;
        float z0f = floorf(iz);
        float wz  = iz - z0f;
        int   z0  = (int)z0f, z1 = z0 + 1;
        float w0  = (z0 >= 0 && z0 < FF) ? (1.f - wz) : 0.f;
        float w1  = (z1 >= 0 && z1 < FF) ? wz         : 0.f;
        int   zb0 = min(max(z0, 0), FF - 1) * PLAY;
        int   zb1 = min(max(z1, 0), FF - 1) * PLAY;

        cfA[f] = make_float4(axx, axy, cx, w0);
        cfB[f] = make_float4(ayx, ayy, cy, w1);
        zb[f]  = make_int2(zb0, zb1);
    }
    __syncthreads();

    const float fx = (float)tx, fy = (float)ty;
    float* outb = out + (size_t)b * VOL + tid;

    #pragma unroll 4
    for (int f = 0; f < FF; f++) {
        float4 A  = cfA[f];
        float4 Bv = cfB[f];
        int2   zo = zb[f];

        float ix = fmaf(A.x,  fx, fmaf(A.y,  fy, A.z));
        float iy = fmaf(Bv.x, fx, fmaf(Bv.y, fy, Bv.z));
        ix = fminf(fmaxf(ix, -1.f), (float)WW);
        iy = fminf(fmaxf(iy, -1.f), (float)HH);

        int   x0 = __float2int_rd(ix);
        int   y0 = __float2int_rd(iy);
        float wx = ix - (float)x0;
        float wy = iy - (float)y0;

        int bo = y0 * PROW + x0 + (PROW + 1);

        float2 f00 = __half22float2(pairs[zo.x + bo]);
        float2 f01 = __half22float2(pairs[zo.x + bo + PROW]);
        float2 f10 = __half22float2(pairs[zo.y + bo]);
        float2 f11 = __half22float2(pairs[zo.y + bo + PROW]);

        float h00 = fmaf(wx, f00.y - f00.x, f00.x);
        float h01 = fmaf(wx, f01.y - f01.x, f01.x);
        float h10 = fmaf(wx, f10.y - f10.x, f10.x);
        float h11 = fmaf(wx, f11.y - f11.x, f11.x);

        float s0 = fmaf(wy, h01 - h00, h00);
        float s1 = fmaf(wy, h11 - h10, h10);

        outb[f * HW] = fmaf(A.w, s0, Bv.w * s1);
    }
}

// ---------------------------------------------------------------------------
// Launch
// ---------------------------------------------------------------------------
extern "C" void kernel_launch(void* const* d_in, const int* in_sizes, int n_in,
                              void* d_out, int out_size)
{
    const float* feature_map = (const float*)d_in[0];
    const float* para_code   = (const float*)d_in[1];
    const float* W1          = (const float*)d_in[2];
    const float* b1          = (const float*)d_in[3];
    const float* Ws          = (const float*)d_in[4];
    const float* bs          = (const float*)d_in[5];
    const float* Wr          = (const float*)d_in[6];
    const float* br          = (const float*)d_in[7];
    const float* Wt          = (const float*)d_in[8];
    const float* bt          = (const float*)d_in[9];
    float*       out         = (float*)d_out;

    int B = in_sizes[1] / PP;
    if (B > MAXB) B = MAXB;

    dim3 g1((B + K1_BM - 1) / K1_BM, NG);
    adaat_hidden_kernel<<<g1, 256>>>(para_code, B, W1, b1, Ws, Wr, Wt);
    adaat_sample_kernel<<<B, dim3(WW, HH)>>>(feature_map, out, bs, br, bt);
}